// round 14
// baseline (speedup 1.0000x reference)
#include <cuda_runtime.h>
#include <cstdint>

#define NQ      14
#define NSTATE  (1 << NQ)          // 16384
#define NLAYERS 6
#define NGATES  (NLAYERS * NQ)     // 84 (RX merged into layer-0 Rot)
#define NPASSES ((NLAYERS - 1) * 3)  // 15: layers 1..5, per layer 2x NW=5 + 1x NW=4
#define TPB     256
#define DYNSM   196608             // 192 KB: guarantees a 64KB-aligned 128KB state window

typedef unsigned long long ull;
typedef unsigned u32;

struct PassP {
    u32 cmb[32];        // byte-scaled slot XOR masks (cm[j]<<2), logical 5-bit index
    u32 r[5];           // parity rows (L^-1)
    u32 f;              // lane1 orientation flip bits (r_k . e_d)
    u32 ddb;            // byte-scaled duo offset (4 << d)
    unsigned char Arl[8];  // stagger relabel index per lane bit (5 used)
    signed   char ep[8];   // sorted insert positions: nw pivots + duo bit d
    unsigned char g[8];    // gate ids (nw used)
    int nw;             // 5 or 4
};
struct Params { PassP p[NPASSES]; u32 rz; };

// ---------------- packed f32x2 helpers ----------------
__device__ __forceinline__ ull pack2f(float lo, float hi) {
    ull r; asm("mov.b64 %0,{%1,%2};" : "=l"(r) : "f"(lo), "f"(hi)); return r;
}
__device__ __forceinline__ void unpack2f(ull v, float& lo, float& hi) {
    asm("mov.b64 {%0,%1},%2;" : "=f"(lo), "=f"(hi) : "l"(v));
}
__device__ __forceinline__ ull ffma2(ull a, ull b, ull c) {
    ull d; asm("fma.rn.f32x2 %0,%1,%2,%3;" : "=l"(d) : "l"(a), "l"(b), "l"(c)); return d;
}
__device__ __forceinline__ ull fmul2(ull a, ull b) {
    ull d; asm("mul.rn.f32x2 %0,%1,%2;" : "=l"(d) : "l"(a), "l"(b)); return d;
}
__device__ __forceinline__ ull neg2(ull a) {
    return a ^ 0x8000000080000000ull;
}

// ---------------- raw shared ld/st (32-bit address space) ----------------
__device__ __forceinline__ float ldsf(u32 a) {
    float v; asm volatile("ld.shared.f32 %0,[%1];" : "=f"(v) : "r"(a)); return v;
}
__device__ __forceinline__ float ldsfI(u32 a) {
    float v; asm volatile("ld.shared.f32 %0,[%1+65536];" : "=f"(v) : "r"(a)); return v;
}
__device__ __forceinline__ void stsf(u32 a, float v) {
    asm volatile("st.shared.f32 [%0],%1;" :: "r"(a), "f"(v));
}
__device__ __forceinline__ void stsfI(u32 a, float v) {
    asm volatile("st.shared.f32 [%0+65536],%1;" :: "r"(a), "f"(v));
}

// 4 stored coeffs per gate (per-lane orientation signs folded into pu, pv)
struct PGd { ull pax, pu, pv, pw; };
// 7-coeff expanded form, built ONCE per gate (3 neg2), zero negs per su2duo
struct PGd7 { ull pax, pu, pnu, pv, pnv, pw, pnw; };

// duo SU(2), SoA lanes = two independent groups.  u=ay, v=bx, w=by.
// nra = ax*ra - u*ia - v*rb - w*ib ; nia = ax*ia + u*ra - v*ib + w*rb
// nrb = ax*rb + u*ib + v*ra - w*ia ; nib = ax*ib - u*rb + v*ia + w*ra
__device__ __forceinline__ void su2duo7(const PGd7& g, ull& ra, ull& ia, ull& rb, ull& ib) {
    ull nra = ffma2(g.pax, ra, ffma2(g.pnu, ia, ffma2(g.pnv, rb, fmul2(g.pnw, ib))));
    ull nia = ffma2(g.pax, ia, ffma2(g.pu,  ra, ffma2(g.pnv, ib, fmul2(g.pw,  rb))));
    ull nrb = ffma2(g.pax, rb, ffma2(g.pu,  ib, ffma2(g.pv,  ra, fmul2(g.pnw, ia))));
    ull nib = ffma2(g.pax, ib, ffma2(g.pnu, rb, ffma2(g.pv,  ia, fmul2(g.pw,  ra))));
    ra = nra; ia = nia; rb = nrb; ib = nib;
}

__device__ __forceinline__ constexpr int ctzc(int t) {
    return (t & 1) ? 0 : (t & 2) ? 1 : (t & 4) ? 2 : (t & 8) ? 3 : 4;
}

// ---------------- pass application (NW = 5 or 4 gates, duo = 2 groups/thread) ----------------
// sbase is 65536-aligned -> all addresses are sbase | off (off < 65536),
// so the gray chain XORs apply directly to full addresses.
template <int NW>
__device__ __forceinline__ void apply_pass(u32 sbase, const float4* gates4,
                                           const PassP& pp, int tid) {
    constexpr int NA  = 1 << NW;
    constexpr int NIT = (NSTATE >> (NW + 1)) / TPB;   // 1 for NW=5, 2 for NW=4

    // per-lane stagger relabel rl (linear: cm[rl] = XOR of cm[Arl[b]])
    const u32 lane = (u32)tid & 31u;
    u32 rl = 0, cofsb = 0;
    #pragma unroll
    for (int b = 0; b < 5; b++) {
        if ((lane >> b) & 1u) { rl ^= pp.Arl[b]; cofsb ^= pp.cmb[pp.Arl[b]]; }
    }

    // gate coefficients: lane0 flip = rl_k, lane1 flip = rl_k ^ f_k
    PGd G[NW];
    #pragma unroll
    for (int k = 0; k < NW; k++) {
        float4 gg = gates4[pp.g[k]];        // (ax, ay=u, bx=v, by=w)
        u32 fl0 = (rl >> k) & 1u;
        u32 fl1 = fl0 ^ ((pp.f >> k) & 1u);
        float u0 = fl0 ? -gg.y : gg.y;
        float u1 = fl1 ? -gg.y : gg.y;
        float v0 = fl0 ? -gg.z : gg.z;
        float v1 = fl1 ? -gg.z : gg.z;
        G[k].pax = pack2f(gg.x, gg.x);
        G[k].pu  = pack2f(u0, u1);
        G[k].pv  = pack2f(v0, v1);
        G[k].pw  = pack2f(gg.w, gg.w);
    }

    u32 dg[NW], mk[NW], rr[NW];
    #pragma unroll
    for (int k = 0; k < NW; k++) {
        dg[k] = pp.cmb[1 << k];
        mk[k] = dg[k] >> 2;
        rr[k] = pp.r[k];
    }
    const u32 ddb = pp.ddb;

    #pragma unroll 1
    for (int it = 0; it < NIT; it++) {
        u32 p = (u32)tid + (u32)(it * TPB);
        // insert zeros at NW+1 sorted positions (pivots + duo bit)
        #pragma unroll
        for (int i = 0; i < NW + 1; i++) {
            int bp = pp.ep[i];
            p = ((p >> bp) << (bp + 1)) | (p & ((1u << bp) - 1u));
        }
        // fold lane0 rep to all-logical-zero (valid: r_i . m_j = delta_ij)
        #pragma unroll
        for (int k = 0; k < NW; k++) {
            u32 s = (u32)(-(int)(__popc(p & rr[k]) & 1));
            p ^= s & mk[k];
        }
        const u32 abase = sbase | ((p << 2) ^ cofsb);   // full address, XOR-pure

        ull vre[NA], vim[NA];
        // gray-order load chain (XOR-only address updates)
        {
            u32 a0 = abase;
            #pragma unroll
            for (int t = 0; t < NA; t++) {
                if (t) a0 ^= dg[ctzc(t)];
                int j = t ^ (t >> 1);
                u32 a1 = a0 ^ ddb;
                vre[j] = pack2f(ldsf(a0),  ldsf(a1));
                vim[j] = pack2f(ldsfI(a0), ldsfI(a1));
            }
        }
        // gates: expand 4 stored coeffs to 7 ONCE per gate, then pure-FMA inner
        #pragma unroll
        for (int k = 0; k < NW; k++) {
            PGd7 g7;
            g7.pax = G[k].pax;
            g7.pu  = G[k].pu;  g7.pnu = neg2(G[k].pu);
            g7.pv  = G[k].pv;  g7.pnv = neg2(G[k].pv);
            g7.pw  = G[k].pw;  g7.pnw = neg2(G[k].pw);
            #pragma unroll
            for (int j = 0; j < NA; j++) {
                if ((j >> k) & 1) continue;
                su2duo7(g7, vre[j], vim[j], vre[j | (1 << k)], vim[j | (1 << k)]);
            }
        }
        // gray-order store chain
        {
            u32 a0 = abase;
            #pragma unroll
            for (int t = 0; t < NA; t++) {
                if (t) a0 ^= dg[ctzc(t)];
                int j = t ^ (t >> 1);
                u32 a1 = a0 ^ ddb;
                float x0, x1, y0, y1;
                unpack2f(vre[j], x0, x1);
                unpack2f(vim[j], y0, y1);
                stsf(a0, x0);  stsf(a1, x1);
                stsfI(a0, y0); stsfI(a1, y1);
            }
        }
    }
}

__device__ __forceinline__ float2 cmul(float2 a, float2 b) {
    return make_float2(a.x * b.x - a.y * b.y, a.x * b.y + a.y * b.x);
}

__global__ void __launch_bounds__(TPB, 1)
qsim_kernel(const float* __restrict__ x, const float* __restrict__ wts,
            float* __restrict__ out, Params P)
{
    extern __shared__ char dynsm[];           // 192 KB; state at 64KB-aligned offset
    __shared__ float4 gates4[NGATES];
    __shared__ float2 tabA[128], tabB[128];   // product-state half tables
    __shared__ float  red[TPB / 32];

    const int tid = threadIdx.x;
    const int b   = blockIdx.x;

    const u32 dynb  = (u32)__cvta_generic_to_shared(dynsm);
    const u32 sbase = (dynb + 65535u) & 0xFFFF0000u;      // 64KB-aligned state base
    float* reP = (float*)(dynsm + (sbase - dynb));         // re plane [16384]
    float* imP = reP + NSTATE;                             // im plane (= sbase+65536)

    // ---- build SU(2) gates: alpha = ax+i*ay, beta = bx+i*by ----
    if (tid < NGATES) {
        int l = tid / NQ, w = tid % NQ;
        const float* ww = wts + tid * 3;
        float phi = ww[0], th = ww[1], om = ww[2];
        float stt, ct, sA, cA, sB, cB;
        sincosf(0.5f * th, &stt, &ct);
        sincosf(0.5f * (phi + om), &sA, &cA);
        sincosf(0.5f * (phi - om), &sB, &cB);
        float2 al = make_float2(ct * cA, -ct * sA);
        float2 be = make_float2(stt * cB, -stt * sB);
        if (l == 0) {
            // merge RX(x_w):  G = Rot * RX
            float s, c;
            sincosf(0.5f * x[b * NQ + w], &s, &c);
            float2 aX = make_float2(c, 0.f), bX = make_float2(0.f, -s);
            float2 cbe = make_float2(be.x, -be.y);
            float2 cal = make_float2(al.x, -al.y);
            float2 t1 = cmul(al, aX), t2 = cmul(cbe, bX);
            float2 aG = make_float2(t1.x - t2.x, t1.y - t2.y);
            float2 t3 = cmul(be, aX), t4 = cmul(cal, bX);
            float2 bG = make_float2(t3.x + t4.x, t3.y + t4.y);
            al = aG; be = bG;
        }
        gates4[tid] = make_float4(al.x, al.y, be.x, be.y);
    }
    __syncthreads();

    // ---- layer 0 as direct product state: amp(p) = prod_w (p_w ? beta_w : alpha_w)
    if (tid < 128) {
        float2 a = make_float2(1.f, 0.f);
        #pragma unroll
        for (int w = 0; w < 7; w++) {
            float4 g = gates4[w];
            float2 sel = ((tid >> w) & 1) ? make_float2(g.z, g.w)
                                          : make_float2(g.x, g.y);
            a = cmul(a, sel);
        }
        tabA[tid] = a;
    } else {
        int t = tid - 128;
        float2 a = make_float2(1.f, 0.f);
        #pragma unroll
        for (int w = 0; w < 7; w++) {
            float4 g = gates4[7 + w];
            float2 sel = ((t >> w) & 1) ? make_float2(g.z, g.w)
                                        : make_float2(g.x, g.y);
            a = cmul(a, sel);
        }
        tabB[t] = a;
    }
    __syncthreads();

    // ---- init state = product ----
    for (int i = tid; i < NSTATE; i += TPB) {
        float2 c = cmul(tabA[i & 127], tabB[i >> 7]);
        reP[i] = c.x;
        imP[i] = c.y;
    }
    __syncthreads();

    // ---- 15 passes (layers 1..5) ----
    #pragma unroll 1
    for (int ps = 0; ps < NPASSES; ps++) {
        const PassP& pp = P.p[ps];
        if (pp.nw == 5) apply_pass<5>(sbase, gates4, pp, tid);
        else            apply_pass<4>(sbase, gates4, pp, tid);
        __syncthreads();
    }

    // ---- <Z_0> ----
    float acc = 0.f;
    const u32 rz = P.rz;
    for (int i = tid; i < NSTATE; i += TPB) {
        float re = reP[i], im = imP[i];
        float pr = fmaf(re, re, im * im);
        acc += (__popc((u32)i & rz) & 1) ? -pr : pr;
    }
    #pragma unroll
    for (int off = 16; off; off >>= 1)
        acc += __shfl_down_sync(0xffffffffu, acc, off);
    if ((tid & 31) == 0) red[tid >> 5] = acc;
    __syncthreads();
    if (tid == 0) {
        float s = 0.f;
        #pragma unroll
        for (int wgi = 0; wgi < TPB / 32; wgi++) s += red[wgi];
        out[b] = s;
    }
}

// ---------------- host precompute ----------------
static inline int ctz32(u32 v) {
    int c = 0; while (!(v & 1u)) { v >>= 1; c++; } return c;
}

static int rankN(const u32* F, int n) {
    u32 a[5];
    for (int i = 0; i < n; i++) a[i] = F[i];
    int r = 0;
    for (int bit = 0; bit < 5; bit++) {
        int s = -1;
        for (int i = r; i < n; i++) if ((a[i] >> bit) & 1u) { s = i; break; }
        if (s < 0) continue;
        u32 t = a[s]; a[s] = a[r]; a[r] = t;
        for (int i = 0; i < n; i++)
            if (i != r && ((a[i] >> bit) & 1u)) a[i] ^= a[r];
        r++;
    }
    return r;
}

// DFS over stagger relabel indices; vb[] already fold-corrected
static bool dfsA(const u32* vb, const u32* cm, int na, u32* F, u32* A, int depth) {
    if (depth == 5) return true;
    for (int a = 0; a < na; a++) {
        F[depth] = (vb[depth] ^ cm[a]) & 31u;
        if (rankN(F, depth + 1) == depth + 1) {
            A[depth] = (u32)a;
            if (dfsA(vb, cm, na, F, A, depth + 1)) return true;
        }
    }
    return false;
}

// sorted insert positions (nw pivots + d) and lane-bit landing masks
static void build_ep_pins(const int* pv, int nw, int d, int* ep, u32* pins) {
    int tmp[6];
    for (int i = 0; i < nw; i++) tmp[i] = pv[i];
    tmp[nw] = d;
    for (int i = 0; i < nw + 1; i++)
        for (int j = i + 1; j < nw + 1; j++)
            if (tmp[j] < tmp[i]) { int t = tmp[i]; tmp[i] = tmp[j]; tmp[j] = t; }
    for (int i = 0; i < 6; i++) ep[i] = (i < nw + 1) ? tmp[i] : 0;
    for (int b = 0; b < 5; b++) {
        int pos = b;
        for (int i = 0; i < nw + 1; i++) if (tmp[i] <= pos) pos++;
        pins[b] = (pos < 32) ? (1u << pos) : 0u;
    }
}

static void fill_pass(PassP& ps, const u32* col, const u32* row,
                      const int* wsel, int nw, int l) {
    u32 m[5], cm[32];
    for (int i = 0; i < nw; i++) {
        m[i]    = col[wsel[i]];
        ps.r[i] = row[wsel[i]];
        ps.g[i] = (unsigned char)(l * NQ + wsel[i]);
    }
    for (int i = nw; i < 5; i++) { ps.r[i] = 0; }
    for (int i = nw; i < 8; i++) { ps.g[i] = 0; }
    int na = 1 << nw;
    for (int j = 0; j < 32; j++) cm[j] = 0;
    for (int j = 0; j < na; j++) {
        u32 c = 0;
        for (int i = 0; i < nw; i++) if ((j >> i) & 1) c ^= m[i];
        cm[j] = c;
    }
    for (int j = 0; j < 32; j++) ps.cmb[j] = cm[j] << 2;

    // pivots via Gaussian elimination
    u32 redm[5]; int pv[5];
    for (int i = 0; i < nw; i++) {
        u32 v = m[i];
        for (int j = 0; j < i; j++)
            if ((v >> pv[j]) & 1u) v ^= redm[j];
        pv[i] = ctz32(v);
        redm[i] = v;
    }
    for (int i = 0; i < nw; i++)
        for (int j = i + 1; j < nw; j++)
            if (pv[j] < pv[i]) { int t = pv[i]; pv[i] = pv[j]; pv[j] = t; }
    ps.nw = nw;

    // try every non-pivot duo bit d; pick the first with a rank-5 stagger.
    // vb includes the parity-fold correction: fold(e_pos) = e_pos ^ XOR_{k: r_k[pos]} m_k
    int  bestd = -1;
    int  ep[6]; u32 pins[5], vb[5], F[5], A[5];
    for (int d = 0; d < NQ; d++) {
        bool ispv = false;
        for (int i = 0; i < nw; i++) if (pv[i] == d) ispv = true;
        if (ispv) continue;
        if (bestd < 0) bestd = d;                 // fallback candidate
        build_ep_pins(pv, nw, d, ep, pins);
        for (int b = 0; b < 5; b++) {
            vb[b] = pins[b];
            if (pins[b]) {
                int pos = ctz32(pins[b]);
                for (int k = 0; k < nw; k++)
                    if ((ps.r[k] >> pos) & 1u) vb[b] ^= m[k];
            }
        }
        if (dfsA(vb, cm, na, F, A, 0)) {
            for (int i = 0; i < 6; i++) ps.ep[i] = (signed char)ep[i];
            for (int i = 6; i < 8; i++) ps.ep[i] = 0;
            for (int i = 0; i < 5; i++) ps.Arl[i] = (unsigned char)A[i];
            for (int i = 5; i < 8; i++) ps.Arl[i] = 0;
            ps.ddb = 4u << d;
            u32 f = 0;
            for (int k = 0; k < nw; k++)
                if ((ps.r[k] >> d) & 1u) f |= 1u << k;
            ps.f = f;
            return;
        }
    }
    // fallback: no conflict-free stagger found (still correct)
    build_ep_pins(pv, nw, bestd, ep, pins);
    for (int i = 0; i < 6; i++) ps.ep[i] = (signed char)ep[i];
    for (int i = 6; i < 8; i++) ps.ep[i] = 0;
    for (int i = 0; i < 8; i++) ps.Arl[i] = 0;
    ps.ddb = 4u << bestd;
    u32 f = 0;
    for (int k = 0; k < nw; k++)
        if ((ps.r[k] >> bestd) & 1u) f |= 1u << k;
    ps.f = f;
}

extern "C" void kernel_launch(void* const* d_in, const int* in_sizes, int n_in,
                              void* d_out, int out_size) {
    const float* x   = (const float*)d_in[0];
    const float* wts = (const float*)d_in[1];
    float*       out = (float*)d_out;
    const int B = in_sizes[0] / NQ;

    Params P;
    u32 col[NQ], row[NQ];
    for (int i = 0; i < NQ; i++) { col[i] = 1u << i; row[i] = 1u << i; }

    // layer 0 handled by product-state init; absorb its CNOT ring first
    {
        int r = 1;
        for (int w = 0; w < NQ; w++) {
            int c = w, t = (w + r) % NQ;
            col[c] ^= col[t];
            row[t] ^= row[c];
        }
    }

    int pi = 0;
    for (int l = 1; l < NLAYERS; l++) {
        static const int g5a[5] = {0,1,2,3,4};
        static const int g5b[5] = {5,6,7,8,9};
        static const int g4c[4] = {10,11,12,13};
        fill_pass(P.p[pi++], col, row, g5a, 5, l);
        fill_pass(P.p[pi++], col, row, g5b, 5, l);
        fill_pass(P.p[pi++], col, row, g4c, 4, l);

        // absorb CNOT ring:  CNOT(c,t): col[c] ^= col[t]; row[t] ^= row[c]
        int r = (l % (NQ - 1)) + 1;
        for (int w = 0; w < NQ; w++) {
            int c = w, t = (w + r) % NQ;
            col[c] ^= col[t];
            row[t] ^= row[c];
        }
    }
    P.rz = row[0];

    cudaFuncSetAttribute(qsim_kernel, cudaFuncAttributeMaxDynamicSharedMemorySize,
                         DYNSM);
    qsim_kernel<<<B, TPB, DYNSM>>>(x, wts, out, P);
}

// round 15
// speedup vs baseline: 1.5999x; 1.5999x over previous
#include <cuda_runtime.h>
#include <cstdint>

#define NQ      14
#define NSTATE  (1 << NQ)          // 16384
#define NLAYERS 6
#define NGATES  (NLAYERS * NQ)     // 84 (RX merged into layer-0 Rot)
#define NPASSES ((NLAYERS - 1) * 3)  // 15: layers 1..5, per layer 2x NW=5 + 1x NW=4
#define TPB     256

typedef unsigned long long ull;
typedef unsigned u32;

struct PassP {
    u32 cmb[32];        // byte-scaled slot XOR masks (cm[j]<<2), logical 5-bit index
    u32 r[5];           // parity rows (L^-1)
    u32 f;              // lane1 orientation flip bits (r_k . e_d)
    u32 ddb;            // byte-scaled duo offset (4 << d)
    unsigned char Arl[8];  // stagger relabel index per lane bit (5 used)
    signed   char ep[8];   // sorted insert positions: nw pivots + duo bit d
    unsigned char g[8];    // gate ids (nw used)
    int nw;             // 5 or 4
};
struct Params { PassP p[NPASSES]; u32 rz; };

// ---------------- packed f32x2 helpers ----------------
__device__ __forceinline__ ull pack2f(float lo, float hi) {
    ull r; asm("mov.b64 %0,{%1,%2};" : "=l"(r) : "f"(lo), "f"(hi)); return r;
}
__device__ __forceinline__ void unpack2f(ull v, float& lo, float& hi) {
    asm("mov.b64 {%0,%1},%2;" : "=f"(lo), "=f"(hi) : "l"(v));
}
__device__ __forceinline__ ull ffma2(ull a, ull b, ull c) {
    ull d; asm("fma.rn.f32x2 %0,%1,%2,%3;" : "=l"(d) : "l"(a), "l"(b), "l"(c)); return d;
}
__device__ __forceinline__ ull fmul2(ull a, ull b) {
    ull d; asm("mul.rn.f32x2 %0,%1,%2;" : "=l"(d) : "l"(a), "l"(b)); return d;
}
// negate both packed lanes (sign-bit XOR; ALU pipe, not FMA)
__device__ __forceinline__ ull neg2(ull a) {
    return a ^ 0x8000000080000000ull;
}

// ---------------- raw shared ld/st (32-bit address space) ----------------
__device__ __forceinline__ float ldsf(u32 a) {
    float v; asm volatile("ld.shared.f32 %0,[%1];" : "=f"(v) : "r"(a)); return v;
}
__device__ __forceinline__ float ldsfI(u32 a) {
    float v; asm volatile("ld.shared.f32 %0,[%1+65536];" : "=f"(v) : "r"(a)); return v;
}
__device__ __forceinline__ void stsf(u32 a, float v) {
    asm volatile("st.shared.f32 [%0],%1;" :: "r"(a), "f"(v));
}
__device__ __forceinline__ void stsfI(u32 a, float v) {
    asm volatile("st.shared.f32 [%0+65536],%1;" :: "r"(a), "f"(v));
}

// 4 stored coeffs per gate (per-lane orientation signs folded into pu, pv)
struct PGd { ull pax, pu, pv, pw; };
// 7-coeff expanded form, built ONCE per gate (3 neg2), zero negs per su2duo
struct PGd7 { ull pax, pu, pnu, pv, pnv, pw, pnw; };

// duo SU(2), SoA lanes = two independent groups.  u=ay, v=bx, w=by.
// nra = ax*ra - u*ia - v*rb - w*ib ; nia = ax*ia + u*ra - v*ib + w*rb
// nrb = ax*rb + u*ib + v*ra - w*ia ; nib = ax*ib - u*rb + v*ia + w*ra
__device__ __forceinline__ void su2duo7(const PGd7& g, ull& ra, ull& ia, ull& rb, ull& ib) {
    ull nra = ffma2(g.pax, ra, ffma2(g.pnu, ia, ffma2(g.pnv, rb, fmul2(g.pnw, ib))));
    ull nia = ffma2(g.pax, ia, ffma2(g.pu,  ra, ffma2(g.pnv, ib, fmul2(g.pw,  rb))));
    ull nrb = ffma2(g.pax, rb, ffma2(g.pu,  ib, ffma2(g.pv,  ra, fmul2(g.pnw, ia))));
    ull nib = ffma2(g.pax, ib, ffma2(g.pnu, rb, ffma2(g.pv,  ia, fmul2(g.pw,  ra))));
    ra = nra; ia = nia; rb = nrb; ib = nib;
}

__device__ __forceinline__ constexpr int ctzc(int t) {
    return (t & 1) ? 0 : (t & 2) ? 1 : (t & 4) ? 2 : (t & 8) ? 3 : 4;
}

// ---------------- pass application (NW = 5 or 4 gates, duo = 2 groups/thread) ----------------
template <int NW>
__device__ __forceinline__ void apply_pass(u32 sbase, const float4* gates4,
                                           const PassP& pp, int tid) {
    constexpr int NA  = 1 << NW;
    constexpr int NIT = (NSTATE >> (NW + 1)) / TPB;   // 1 for NW=5, 2 for NW=4

    // per-lane stagger relabel rl (linear: cm[rl] = XOR of cm[Arl[b]])
    const u32 lane = (u32)tid & 31u;
    u32 rl = 0, cofsb = 0;
    #pragma unroll
    for (int b = 0; b < 5; b++) {
        if ((lane >> b) & 1u) { rl ^= pp.Arl[b]; cofsb ^= pp.cmb[pp.Arl[b]]; }
    }

    // gate coefficients: lane0 flip = rl_k, lane1 flip = rl_k ^ f_k
    PGd G[NW];
    #pragma unroll
    for (int k = 0; k < NW; k++) {
        float4 gg = gates4[pp.g[k]];        // (ax, ay=u, bx=v, by=w)
        u32 fl0 = (rl >> k) & 1u;
        u32 fl1 = fl0 ^ ((pp.f >> k) & 1u);
        float u0 = fl0 ? -gg.y : gg.y;
        float u1 = fl1 ? -gg.y : gg.y;
        float v0 = fl0 ? -gg.z : gg.z;
        float v1 = fl1 ? -gg.z : gg.z;
        G[k].pax = pack2f(gg.x, gg.x);
        G[k].pu  = pack2f(u0, u1);
        G[k].pv  = pack2f(v0, v1);
        G[k].pw  = pack2f(gg.w, gg.w);
    }

    u32 dg[NW], mk[NW], rr[NW];
    #pragma unroll
    for (int k = 0; k < NW; k++) {
        dg[k] = pp.cmb[1 << k];
        mk[k] = dg[k] >> 2;
        rr[k] = pp.r[k];
    }
    const u32 ddb = pp.ddb;

    #pragma unroll 1
    for (int it = 0; it < NIT; it++) {
        u32 p = (u32)tid + (u32)(it * TPB);
        // insert zeros at NW+1 sorted positions (pivots + duo bit)
        #pragma unroll
        for (int i = 0; i < NW + 1; i++) {
            int bp = pp.ep[i];
            p = ((p >> bp) << (bp + 1)) | (p & ((1u << bp) - 1u));
        }
        // fold lane0 rep to all-logical-zero (valid: r_i . m_j = delta_ij)
        #pragma unroll
        for (int k = 0; k < NW; k++) {
            u32 s = (u32)(-(int)(__popc(p & rr[k]) & 1));
            p ^= s & mk[k];
        }
        u32 off = (p << 2) ^ cofsb;          // byte offset incl. stagger

        ull vre[NA], vim[NA];
        // gray-order load chain
        {
            u32 o = off;
            #pragma unroll
            for (int t = 0; t < NA; t++) {
                if (t) o ^= dg[ctzc(t)];
                int j = t ^ (t >> 1);
                u32 a0 = sbase + o;
                u32 a1 = sbase + (o ^ ddb);
                vre[j] = pack2f(ldsf(a0),  ldsf(a1));
                vim[j] = pack2f(ldsfI(a0), ldsfI(a1));
            }
        }
        // gates: expand 4 stored coeffs to 7 ONCE per gate, then pure-FMA inner
        #pragma unroll
        for (int k = 0; k < NW; k++) {
            PGd7 g7;
            g7.pax = G[k].pax;
            g7.pu  = G[k].pu;  g7.pnu = neg2(G[k].pu);
            g7.pv  = G[k].pv;  g7.pnv = neg2(G[k].pv);
            g7.pw  = G[k].pw;  g7.pnw = neg2(G[k].pw);
            #pragma unroll
            for (int j = 0; j < NA; j++) {
                if ((j >> k) & 1) continue;
                su2duo7(g7, vre[j], vim[j], vre[j | (1 << k)], vim[j | (1 << k)]);
            }
        }
        // gray-order store chain
        {
            u32 o = off;
            #pragma unroll
            for (int t = 0; t < NA; t++) {
                if (t) o ^= dg[ctzc(t)];
                int j = t ^ (t >> 1);
                u32 a0 = sbase + o;
                u32 a1 = sbase + (o ^ ddb);
                float x0, x1, y0, y1;
                unpack2f(vre[j], x0, x1);
                unpack2f(vim[j], y0, y1);
                stsf(a0, x0);  stsf(a1, x1);
                stsfI(a0, y0); stsfI(a1, y1);
            }
        }
    }
}

__device__ __forceinline__ float2 cmul(float2 a, float2 b) {
    return make_float2(a.x * b.x - a.y * b.y, a.x * b.y + a.y * b.x);
}

__global__ void __launch_bounds__(TPB, 1)
qsim_kernel(const float* __restrict__ x, const float* __restrict__ wts,
            float* __restrict__ out, Params P)
{
    extern __shared__ float smemf[];          // [0,16384): re   [16384,32768): im
    __shared__ float4 gates4[NGATES];
    __shared__ float2 tabA[128], tabB[128];   // product-state half tables
    __shared__ float  red[TPB / 32];

    const int tid = threadIdx.x;
    const int b   = blockIdx.x;
    const u32 sbase = (u32)__cvta_generic_to_shared(smemf);

    // ---- build SU(2) gates: alpha = ax+i*ay, beta = bx+i*by ----
    if (tid < NGATES) {
        int l = tid / NQ, w = tid % NQ;
        const float* ww = wts + tid * 3;
        float phi = ww[0], th = ww[1], om = ww[2];
        float stt, ct, sA, cA, sB, cB;
        sincosf(0.5f * th, &stt, &ct);
        sincosf(0.5f * (phi + om), &sA, &cA);
        sincosf(0.5f * (phi - om), &sB, &cB);
        float2 al = make_float2(ct * cA, -ct * sA);
        float2 be = make_float2(stt * cB, -stt * sB);
        if (l == 0) {
            // merge RX(x_w):  G = Rot * RX
            float s, c;
            sincosf(0.5f * x[b * NQ + w], &s, &c);
            float2 aX = make_float2(c, 0.f), bX = make_float2(0.f, -s);
            float2 cbe = make_float2(be.x, -be.y);
            float2 cal = make_float2(al.x, -al.y);
            float2 t1 = cmul(al, aX), t2 = cmul(cbe, bX);
            float2 aG = make_float2(t1.x - t2.x, t1.y - t2.y);
            float2 t3 = cmul(be, aX), t4 = cmul(cal, bX);
            float2 bG = make_float2(t3.x + t4.x, t3.y + t4.y);
            al = aG; be = bG;
        }
        gates4[tid] = make_float4(al.x, al.y, be.x, be.y);
    }
    __syncthreads();

    // ---- layer 0 as direct product state: amp(p) = prod_w (p_w ? beta_w : alpha_w)
    // half tables: A over wires 0..6, B over wires 7..13
    if (tid < 128) {
        float2 a = make_float2(1.f, 0.f);
        #pragma unroll
        for (int w = 0; w < 7; w++) {
            float4 g = gates4[w];
            float2 sel = ((tid >> w) & 1) ? make_float2(g.z, g.w)
                                          : make_float2(g.x, g.y);
            a = cmul(a, sel);
        }
        tabA[tid] = a;
    } else {
        int t = tid - 128;
        float2 a = make_float2(1.f, 0.f);
        #pragma unroll
        for (int w = 0; w < 7; w++) {
            float4 g = gates4[7 + w];
            float2 sel = ((t >> w) & 1) ? make_float2(g.z, g.w)
                                        : make_float2(g.x, g.y);
            a = cmul(a, sel);
        }
        tabB[t] = a;
    }
    __syncthreads();

    // ---- init state = product ----
    for (int i = tid; i < NSTATE; i += TPB) {
        float2 c = cmul(tabA[i & 127], tabB[i >> 7]);
        smemf[i]          = c.x;
        smemf[NSTATE + i] = c.y;
    }
    __syncthreads();

    // ---- 15 passes (layers 1..5) ----
    #pragma unroll 1
    for (int ps = 0; ps < NPASSES; ps++) {
        const PassP& pp = P.p[ps];
        if (pp.nw == 5) apply_pass<5>(sbase, gates4, pp, tid);
        else            apply_pass<4>(sbase, gates4, pp, tid);
        __syncthreads();
    }

    // ---- <Z_0> ----
    float acc = 0.f;
    const u32 rz = P.rz;
    for (int i = tid; i < NSTATE; i += TPB) {
        float re = smemf[i], im = smemf[NSTATE + i];
        float pr = fmaf(re, re, im * im);
        acc += (__popc((u32)i & rz) & 1) ? -pr : pr;
    }
    #pragma unroll
    for (int off = 16; off; off >>= 1)
        acc += __shfl_down_sync(0xffffffffu, acc, off);
    if ((tid & 31) == 0) red[tid >> 5] = acc;
    __syncthreads();
    if (tid == 0) {
        float s = 0.f;
        #pragma unroll
        for (int wgi = 0; wgi < TPB / 32; wgi++) s += red[wgi];
        out[b] = s;
    }
}

// ---------------- host precompute ----------------
static inline int ctz32(u32 v) {
    int c = 0; while (!(v & 1u)) { v >>= 1; c++; } return c;
}

static int rankN(const u32* F, int n) {
    u32 a[5];
    for (int i = 0; i < n; i++) a[i] = F[i];
    int r = 0;
    for (int bit = 0; bit < 5; bit++) {
        int s = -1;
        for (int i = r; i < n; i++) if ((a[i] >> bit) & 1u) { s = i; break; }
        if (s < 0) continue;
        u32 t = a[s]; a[s] = a[r]; a[r] = t;
        for (int i = 0; i < n; i++)
            if (i != r && ((a[i] >> bit) & 1u)) a[i] ^= a[r];
        r++;
    }
    return r;
}

// DFS over stagger relabel indices; vb[] already fold-corrected
static bool dfsA(const u32* vb, const u32* cm, int na, u32* F, u32* A, int depth) {
    if (depth == 5) return true;
    for (int a = 0; a < na; a++) {
        F[depth] = (vb[depth] ^ cm[a]) & 31u;
        if (rankN(F, depth + 1) == depth + 1) {
            A[depth] = (u32)a;
            if (dfsA(vb, cm, na, F, A, depth + 1)) return true;
        }
    }
    return false;
}

// sorted insert positions (nw pivots + d) and lane-bit landing masks
static void build_ep_pins(const int* pv, int nw, int d, int* ep, u32* pins) {
    int tmp[6];
    for (int i = 0; i < nw; i++) tmp[i] = pv[i];
    tmp[nw] = d;
    for (int i = 0; i < nw + 1; i++)
        for (int j = i + 1; j < nw + 1; j++)
            if (tmp[j] < tmp[i]) { int t = tmp[i]; tmp[i] = tmp[j]; tmp[j] = t; }
    for (int i = 0; i < 6; i++) ep[i] = (i < nw + 1) ? tmp[i] : 0;
    for (int b = 0; b < 5; b++) {
        int pos = b;
        for (int i = 0; i < nw + 1; i++) if (tmp[i] <= pos) pos++;
        pins[b] = (pos < 32) ? (1u << pos) : 0u;
    }
}

static void fill_pass(PassP& ps, const u32* col, const u32* row,
                      const int* wsel, int nw, int l) {
    u32 m[5], cm[32];
    for (int i = 0; i < nw; i++) {
        m[i]    = col[wsel[i]];
        ps.r[i] = row[wsel[i]];
        ps.g[i] = (unsigned char)(l * NQ + wsel[i]);
    }
    for (int i = nw; i < 5; i++) { ps.r[i] = 0; }
    for (int i = nw; i < 8; i++) { ps.g[i] = 0; }
    int na = 1 << nw;
    for (int j = 0; j < 32; j++) cm[j] = 0;
    for (int j = 0; j < na; j++) {
        u32 c = 0;
        for (int i = 0; i < nw; i++) if ((j >> i) & 1) c ^= m[i];
        cm[j] = c;
    }
    for (int j = 0; j < 32; j++) ps.cmb[j] = cm[j] << 2;

    // pivots via Gaussian elimination
    u32 redm[5]; int pv[5];
    for (int i = 0; i < nw; i++) {
        u32 v = m[i];
        for (int j = 0; j < i; j++)
            if ((v >> pv[j]) & 1u) v ^= redm[j];
        pv[i] = ctz32(v);
        redm[i] = v;
    }
    for (int i = 0; i < nw; i++)
        for (int j = i + 1; j < nw; j++)
            if (pv[j] < pv[i]) { int t = pv[i]; pv[i] = pv[j]; pv[j] = t; }
    ps.nw = nw;

    // try every non-pivot duo bit d; pick the first with a rank-5 stagger.
    // vb includes the parity-fold correction: fold(e_pos) = e_pos ^ XOR_{k: r_k[pos]} m_k
    int  bestd = -1;
    int  ep[6]; u32 pins[5], vb[5], F[5], A[5];
    for (int d = 0; d < NQ; d++) {
        bool ispv = false;
        for (int i = 0; i < nw; i++) if (pv[i] == d) ispv = true;
        if (ispv) continue;
        if (bestd < 0) bestd = d;                 // fallback candidate
        build_ep_pins(pv, nw, d, ep, pins);
        for (int b = 0; b < 5; b++) {
            vb[b] = pins[b];
            if (pins[b]) {
                int pos = ctz32(pins[b]);
                for (int k = 0; k < nw; k++)
                    if ((ps.r[k] >> pos) & 1u) vb[b] ^= m[k];
            }
        }
        if (dfsA(vb, cm, na, F, A, 0)) {
            for (int i = 0; i < 6; i++) ps.ep[i] = (signed char)ep[i];
            for (int i = 6; i < 8; i++) ps.ep[i] = 0;
            for (int i = 0; i < 5; i++) ps.Arl[i] = (unsigned char)A[i];
            for (int i = 5; i < 8; i++) ps.Arl[i] = 0;
            ps.ddb = 4u << d;
            u32 f = 0;
            for (int k = 0; k < nw; k++)
                if ((ps.r[k] >> d) & 1u) f |= 1u << k;
            ps.f = f;
            return;
        }
    }
    // fallback: no conflict-free stagger found (still correct)
    build_ep_pins(pv, nw, bestd, ep, pins);
    for (int i = 0; i < 6; i++) ps.ep[i] = (signed char)ep[i];
    for (int i = 6; i < 8; i++) ps.ep[i] = 0;
    for (int i = 0; i < 8; i++) ps.Arl[i] = 0;
    ps.ddb = 4u << bestd;
    u32 f = 0;
    for (int k = 0; k < nw; k++)
        if ((ps.r[k] >> bestd) & 1u) f |= 1u << k;
    ps.f = f;
}

extern "C" void kernel_launch(void* const* d_in, const int* in_sizes, int n_in,
                              void* d_out, int out_size) {
    const float* x   = (const float*)d_in[0];
    const float* wts = (const float*)d_in[1];
    float*       out = (float*)d_out;
    const int B = in_sizes[0] / NQ;

    Params P;
    u32 col[NQ], row[NQ];
    for (int i = 0; i < NQ; i++) { col[i] = 1u << i; row[i] = 1u << i; }

    // layer 0 handled by product-state init; absorb its CNOT ring first
    {
        int r = 1;
        for (int w = 0; w < NQ; w++) {
            int c = w, t = (w + r) % NQ;
            col[c] ^= col[t];
            row[t] ^= row[c];
        }
    }

    int pi = 0;
    for (int l = 1; l < NLAYERS; l++) {
        static const int g5a[5] = {0,1,2,3,4};
        static const int g5b[5] = {5,6,7,8,9};
        static const int g4c[4] = {10,11,12,13};
        fill_pass(P.p[pi++], col, row, g5a, 5, l);
        fill_pass(P.p[pi++], col, row, g5b, 5, l);
        fill_pass(P.p[pi++], col, row, g4c, 4, l);

        // absorb CNOT ring:  CNOT(c,t): col[c] ^= col[t]; row[t] ^= row[c]
        int r = (l % (NQ - 1)) + 1;
        for (int w = 0; w < NQ; w++) {
            int c = w, t = (w + r) % NQ;
            col[c] ^= col[t];
            row[t] ^= row[c];
        }
    }
    P.rz = row[0];

    const size_t smem = 2 * NSTATE * sizeof(float);   // 131072 B
    cudaFuncSetAttribute(qsim_kernel, cudaFuncAttributeMaxDynamicSharedMemorySize,
                         (int)smem);
    qsim_kernel<<<B, TPB, smem>>>(x, wts, out, P);
}